// round 11
// baseline (speedup 1.0000x reference)
#include <cuda_runtime.h>
#include <cuda_fp16.h>
#include <math.h>

#define N_IMG 128
#define N_ANG 285
#define N_DET 183
#define N_T   384

#define PITCHE 133                 // 8-byte entries per row
#define TROWS  34                  // local padded rows 0..33 (global 32q..32q+33)
#define SMEM_E     (TROWS * PITCHE)
#define SMEM_BYTES (SMEM_E * 8)    // 36176 B

#define THREADS 384                // 2 k-segments x 192 threads

__global__ __launch_bounds__(THREADS)
void radon_fwd_kernel(const float* __restrict__ x, float* __restrict__ out) {
    extern __shared__ uint2 simg[];    // entry = {half2 AB, half2 CD}
    __shared__ float geo[8];

    const int tid = threadIdx.x;
    const int ang = blockIdx.x;
    const int bq  = blockIdx.y;        // batch quad (0..1)
    const int qz  = blockIdx.z;        // image quarter (0..3)

    const double RHO = 20.0 * sqrt(2.0);
    const double DX  = 0.3125;
    const double DT  = 2.0 * RHO / (double)N_T;
    const float  SCALE = (float)(DT / 12.0);
    const float  RHOf  = (float)RHO;
    const float  DSf   = (float)(2.0 * RHO / (double)N_DET);

    if (tid == 0) {
        double a = ((double)ang + 0.5) * M_PI / (double)N_ANG;
        double dsin = sin(a), dcos = cos(a);
        double tb = -RHO + 0.5 * DT;
        double st0 = DT * dcos / DX;
        double st1 = DT * dsin / DX;
        geo[0] = (float)(-dsin / DX);
        geo[1] = (float)((tb * dcos + 20.0) / DX + 0.5);   // global padded row base
        geo[2] = (float)( dcos / DX);
        geo[3] = (float)((tb * dsin + 20.0) / DX + 0.5);
        geo[4] = (float)st0;
        geo[5] = (float)st1;
        geo[6] = (fabs(st0) < 1e-9) ? 0.0f : (float)(1.0 / st0);
        geo[7] = (fabs(st1) < 1e-9) ? 0.0f : (float)(1.0 / st1);
    }

    // Fill tile: local row lr <-> global padded row 32q+lr <-> image row ir=32q+lr-1
    {
        const float4* i0 = (const float4*)(x + (size_t)(4 * bq + 0) * N_IMG * N_IMG);
        const float4* i1 = (const float4*)(x + (size_t)(4 * bq + 1) * N_IMG * N_IMG);
        const float4* i2 = (const float4*)(x + (size_t)(4 * bq + 2) * N_IMG * N_IMG);
        const float4* i3 = (const float4*)(x + (size_t)(4 * bq + 3) * N_IMG * N_IMG);
        for (int qd = tid; qd < TROWS * 32; qd += THREADS) {
            int lr = qd >> 5;                  // local row 0..33
            int c4 = qd & 31;                  // float4 col
            int ir = 32 * qz + lr - 1;         // image row
            uint2* dst = &simg[lr * PITCHE + (c4 << 2) + 1];
            if (ir >= 0 && ir < N_IMG) {
                int qi = ir * 32 + c4;
                float4 a4 = i0[qi];
                float4 b4 = i1[qi];
                float4 c4v = i2[qi];
                float4 d4 = i3[qi];
                uint2 e; __half2 t;
                t = __floats2half2_rn(a4.x, b4.x); e.x = *(unsigned*)&t;
                t = __floats2half2_rn(c4v.x, d4.x); e.y = *(unsigned*)&t; dst[0] = e;
                t = __floats2half2_rn(a4.y, b4.y); e.x = *(unsigned*)&t;
                t = __floats2half2_rn(c4v.y, d4.y); e.y = *(unsigned*)&t; dst[1] = e;
                t = __floats2half2_rn(a4.z, b4.z); e.x = *(unsigned*)&t;
                t = __floats2half2_rn(c4v.z, d4.z); e.y = *(unsigned*)&t; dst[2] = e;
                t = __floats2half2_rn(a4.w, b4.w); e.x = *(unsigned*)&t;
                t = __floats2half2_rn(c4v.w, d4.w); e.y = *(unsigned*)&t; dst[3] = e;
            } else {
                const uint2 z = make_uint2(0u, 0u);
                dst[0] = z; dst[1] = z; dst[2] = z; dst[3] = z;
            }
        }
        // side border cols 0 and 129
        const uint2 z = make_uint2(0u, 0u);
        for (int r = tid; r < TROWS; r += THREADS) {
            simg[r * PITCHE] = z;
            simg[r * PITCHE + 129] = z;
        }
    }
    __syncthreads();

    const int det = tid % 192;
    const int seg = tid / 192;

    if (det < N_DET) {
        const float g0 = geo[0], g1 = geo[1], g2 = geo[2], g3 = geo[3];
        const float s0 = geo[4], s1 = geo[5], is0 = geo[6], is1 = geo[7];
        const float EPSf = 1e-3f;

        float s  = fmaf((float)det + 0.5f, DSf, -RHOf);
        float b0 = fmaf(s, g0, g1);
        float b1 = fmaf(s, g2, g3);

        // quarter row boundaries (bit-identical across adjacent CTAs)
        const float RL = (qz == 0) ? EPSf : (32.0f * (float)qz + 0.5f);
        const float RU = (qz == 3) ? (129.0f - EPSf) : (32.0f * (float)qz + 32.5f);

        float lo = (float)(seg * 192);
        float hi = lo + 192.0f;

        bool empty = false;
        if (is0 != 0.0f) {
            float kL = (RL - b0) * is0;
            float kU = (RU - b0) * is0;
            lo = fmaxf(lo, fminf(kL, kU));
            hi = fminf(hi, fmaxf(kL, kU));
        } else {
            empty = !(b0 >= RL && b0 < RU);
        }
        if (is1 != 0.0f) {
            float t0 = (EPSf - b1) * is1;
            float t1 = ((129.0f - EPSf) - b1) * is1;
            lo = fmaxf(lo, fminf(t0, t1));
            hi = fminf(hi, fmaxf(t0, t1));
        } else if (b1 < EPSf || b1 > 129.0f - EPSf) {
            empty = true;
        }

        int klo = (int)ceilf(lo);
        int khi = (int)ceilf(hi);
        if (klo < 0) klo = 0;
        if (khi > N_T) khi = N_T;
        if (empty || khi < klo) khi = klo;
        int n = khi - klo;

        if (n > 0) {
            const float bl0  = b0 - 32.0f * (float)qz;  // local padded row base
            const float bl0p = bl0 + s0;
            const float b1p  = b1 + s1;

            float accA = 0.0f, accB = 0.0f, accC = 0.0f, accD = 0.0f;

            #define SAMPLE(F0, F1, RAB, RCD)                                       \
            {                                                                      \
                float fl0 = floorf(F0);                                            \
                float fl1 = floorf(F1);                                            \
                float fa  = (F0) - fl0;                                            \
                float fb  = (F1) - fl1;                                            \
                int boff = (int)fmaf(fl0, (float)(PITCHE * 8), fl1 * 8.0f);        \
                const uint2* p = (const uint2*)((const char*)simg + boff);         \
                uint2 w00 = p[0];                                                  \
                uint2 w01 = p[1];                                                  \
                uint2 w10 = p[PITCHE];                                             \
                uint2 w11 = p[PITCHE + 1];                                         \
                __half2 b2 = __float2half2_rn(fb);                                 \
                __half2 a2 = __float2half2_rn(fa);                                 \
                __half2 u00 = *(__half2*)&w00.x, q00 = *(__half2*)&w00.y;          \
                __half2 u01 = *(__half2*)&w01.x, q01 = *(__half2*)&w01.y;          \
                __half2 u10 = *(__half2*)&w10.x, q10 = *(__half2*)&w10.y;          \
                __half2 u11 = *(__half2*)&w11.x, q11 = *(__half2*)&w11.y;          \
                __half2 t0 = __hfma2(b2, __hsub2(u01, u00), u00);                  \
                __half2 t1 = __hfma2(b2, __hsub2(u11, u10), u10);                  \
                RAB = __hfma2(a2, __hsub2(t1, t0), t0);                            \
                __half2 t2 = __hfma2(b2, __hsub2(q01, q00), q00);                  \
                __half2 t3 = __hfma2(b2, __hsub2(q11, q10), q10);                  \
                RCD = __hfma2(a2, __hsub2(t3, t2), t2);                            \
            }

            float kf = (float)klo;
            int npair = n >> 1;
            #pragma unroll 2
            for (int it = 0; it < npair; ++it, kf += 2.0f) {
                float f0a = fmaf(kf, s0, bl0);
                float f1a = fmaf(kf, s1, b1);
                float f0b = fmaf(kf, s0, bl0p);
                float f1b = fmaf(kf, s1, b1p);
                __half2 rab0, rcd0, rab1, rcd1;
                SAMPLE(f0a, f1a, rab0, rcd0)
                SAMPLE(f0b, f1b, rab1, rcd1)
                __half2 rab = __hadd2(rab0, rab1);
                __half2 rcd = __hadd2(rcd0, rcd1);
                float2 fab = __half22float2(rab);
                float2 fcd = __half22float2(rcd);
                accA += fab.x; accB += fab.y;
                accC += fcd.x; accD += fcd.y;
            }
            if (n & 1) {
                float f0a = fmaf(kf, s0, bl0);
                float f1a = fmaf(kf, s1, b1);
                __half2 rab, rcd;
                SAMPLE(f0a, f1a, rab, rcd)
                float2 fab = __half22float2(rab);
                float2 fcd = __half22float2(rcd);
                accA += fab.x; accB += fab.y;
                accC += fcd.x; accD += fcd.y;
            }
            #undef SAMPLE

            size_t stride = (size_t)N_ANG * N_DET;
            size_t o = ((size_t)(4 * bq) * N_ANG + ang) * N_DET + det;
            atomicAdd(&out[o],              accA * SCALE);
            atomicAdd(&out[o + stride],     accB * SCALE);
            atomicAdd(&out[o + 2 * stride], accC * SCALE);
            atomicAdd(&out[o + 3 * stride], accD * SCALE);
        }
    }
}

extern "C" void kernel_launch(void* const* d_in, const int* in_sizes, int n_in,
                              void* d_out, int out_size) {
    const float* x = (const float*)d_in[0];
    float* out = (float*)d_out;
    cudaFuncSetAttribute(radon_fwd_kernel,
                         cudaFuncAttributeMaxDynamicSharedMemorySize, SMEM_BYTES);
    cudaMemsetAsync(d_out, 0, (size_t)out_size * sizeof(float), 0);
    dim3 grid(N_ANG, 2, 4);
    radon_fwd_kernel<<<grid, THREADS, SMEM_BYTES>>>(x, out);
}

// round 13
// speedup vs baseline: 1.3208x; 1.3208x over previous
#include <cuda_runtime.h>
#include <cuda_fp16.h>
#include <math.h>

#define N_IMG 128
#define N_ANG 285
#define N_DET 183
#define N_T   384

#define PITCHE 133                 // 8-byte entries per row
#define TROWS  66                  // local padded rows 0..65
#define SMEM_E     (TROWS * PITCHE)
#define SMEM_BYTES (SMEM_E * 8)    // 70224 B -> 3 CTAs/SM

#define THREADS 384                // 12 warps; warp = 8 detectors x 4 k-lanes

__global__ __launch_bounds__(THREADS)
void radon_fwd_kernel(const float* __restrict__ x, float* __restrict__ out) {
    extern __shared__ uint2 simg[];    // entry = {half2 AB, half2 CD}
    __shared__ float geo[8];

    const int tid = threadIdx.x;
    const int ang = blockIdx.x;
    const int bq  = blockIdx.y;        // batch quad (0..1)
    const int h   = blockIdx.z;        // image half (0..1)

    const double RHO = 20.0 * sqrt(2.0);
    const double DX  = 0.3125;
    const double DT  = 2.0 * RHO / (double)N_T;
    const float  SCALE = (float)(DT / 12.0);
    const float  RHOf  = (float)RHO;
    const float  DSf   = (float)(2.0 * RHO / (double)N_DET);

    if (tid == 0) {
        double a = ((double)ang + 0.5) * M_PI / (double)N_ANG;
        double dsin = sin(a), dcos = cos(a);
        double tb = -RHO + 0.5 * DT;
        double st0 = DT * dcos / DX;
        double st1 = DT * dsin / DX;
        geo[0] = (float)(-dsin / DX);
        geo[1] = (float)((tb * dcos + 20.0) / DX + 0.5);
        geo[2] = (float)( dcos / DX);
        geo[3] = (float)((tb * dsin + 20.0) / DX + 0.5);
        geo[4] = (float)st0;
        geo[5] = (float)st1;
        geo[6] = (fabs(st0) < 1e-9) ? 0.0f : (float)(1.0 / st0);
        geo[7] = (fabs(st1) < 1e-9) ? 0.0f : (float)(1.0 / st1);
    }

    // Fill: image rows [63h, 63h+64] -> local rows ir+1-64h, 4 batches packed
    {
        const float4* i0 = (const float4*)(x + (size_t)(4 * bq + 0) * N_IMG * N_IMG);
        const float4* i1 = (const float4*)(x + (size_t)(4 * bq + 1) * N_IMG * N_IMG);
        const float4* i2 = (const float4*)(x + (size_t)(4 * bq + 2) * N_IMG * N_IMG);
        const float4* i3 = (const float4*)(x + (size_t)(4 * bq + 3) * N_IMG * N_IMG);
        const int ir0 = 63 * h;
        for (int q = tid; q < 65 * 32; q += THREADS) {
            int ir = ir0 + (q >> 5);
            int c  = (q & 31) << 2;
            int qi = ir * 32 + (q & 31);
            float4 a4 = i0[qi];
            float4 b4 = i1[qi];
            float4 c4 = i2[qi];
            float4 d4 = i3[qi];
            int lr = ir + 1 - 64 * h;
            uint2* dst = &simg[lr * PITCHE + (c + 1)];
            uint2 e; __half2 t;
            t = __floats2half2_rn(a4.x, b4.x); e.x = *(unsigned*)&t;
            t = __floats2half2_rn(c4.x, d4.x); e.y = *(unsigned*)&t; dst[0] = e;
            t = __floats2half2_rn(a4.y, b4.y); e.x = *(unsigned*)&t;
            t = __floats2half2_rn(c4.y, d4.y); e.y = *(unsigned*)&t; dst[1] = e;
            t = __floats2half2_rn(a4.z, b4.z); e.x = *(unsigned*)&t;
            t = __floats2half2_rn(c4.z, d4.z); e.y = *(unsigned*)&t; dst[2] = e;
            t = __floats2half2_rn(a4.w, b4.w); e.x = *(unsigned*)&t;
            t = __floats2half2_rn(c4.w, d4.w); e.y = *(unsigned*)&t; dst[3] = e;
        }
    }
    // Zero readable border: one full row + side cols
    {
        const uint2 z = make_uint2(0u, 0u);
        const int zrow = 65 * h;
        for (int c = tid; c < 130; c += THREADS)
            simg[zrow * PITCHE + c] = z;
        for (int r = tid; r < TROWS; r += THREADS) {
            simg[r * PITCHE] = z;
            simg[r * PITCHE + 129] = z;
        }
    }
    __syncthreads();

    const int lane  = tid & 31;
    const int wrp   = tid >> 5;          // 0..11
    const int dsub  = lane >> 2;         // 0..7
    const int ksub  = lane & 3;          // 0..3

    const float g0 = geo[0], g1 = geo[1], g2 = geo[2], g3 = geo[3];
    const float s0 = geo[4], s1 = geo[5], is0 = geo[6], is1 = geo[7];
    const float EPSf = 1e-3f;
    const float RL = (h == 0) ? EPSf : 64.5f;
    const float RU = (h == 0) ? 64.5f : (129.0f - EPSf);

    #define SAMPLE(F0, F1, RAB, RCD)                                       \
    {                                                                      \
        float fl0 = floorf(F0);                                            \
        float fl1 = floorf(F1);                                            \
        float fa  = (F0) - fl0;                                            \
        float fb  = (F1) - fl1;                                            \
        int boff = (int)fmaf(fl0, (float)(PITCHE * 8), fl1 * 8.0f);        \
        const uint2* p = (const uint2*)((const char*)simg + boff);         \
        uint2 w00 = p[0];                                                  \
        uint2 w01 = p[1];                                                  \
        uint2 w10 = p[PITCHE];                                             \
        uint2 w11 = p[PITCHE + 1];                                         \
        __half2 b2 = __float2half2_rn(fb);                                 \
        __half2 a2 = __float2half2_rn(fa);                                 \
        __half2 u00 = *(__half2*)&w00.x, q00 = *(__half2*)&w00.y;          \
        __half2 u01 = *(__half2*)&w01.x, q01 = *(__half2*)&w01.y;          \
        __half2 u10 = *(__half2*)&w10.x, q10 = *(__half2*)&w10.y;          \
        __half2 u11 = *(__half2*)&w11.x, q11 = *(__half2*)&w11.y;          \
        __half2 t0 = __hfma2(b2, __hsub2(u01, u00), u00);                  \
        __half2 t1 = __hfma2(b2, __hsub2(u11, u10), u10);                  \
        RAB = __hfma2(a2, __hsub2(t1, t0), t0);                            \
        __half2 t2 = __hfma2(b2, __hsub2(q01, q00), q00);                  \
        __half2 t3 = __hfma2(b2, __hsub2(q11, q10), q10);                  \
        RCD = __hfma2(a2, __hsub2(t3, t2), t2);                            \
    }

    #pragma unroll
    for (int pass = 0; pass < 2; ++pass) {
        int det = pass * 96 + wrp * 8 + dsub;
        bool dok = det < N_DET;

        float b0 = 0.0f, b1 = 0.0f;
        int klo = N_T, khi = 0;          // idle default: extends nothing
        if (dok) {
            float s = fmaf((float)det + 0.5f, DSf, -RHOf);
            b0 = fmaf(s, g0, g1);        // global padded row base
            b1 = fmaf(s, g2, g3);        // global padded col base

            float lo = 0.0f, hi = (float)N_T;
            bool empty = false;
            if (is0 != 0.0f) {
                float kL = (RL - b0) * is0;
                float kU = (RU - b0) * is0;
                lo = fmaxf(lo, fminf(kL, kU));
                hi = fminf(hi, fmaxf(kL, kU));
            } else {
                empty = !(b0 >= RL && b0 < RU);
            }
            if (is1 != 0.0f) {
                float t0 = (EPSf - b1) * is1;
                float t1 = ((129.0f - EPSf) - b1) * is1;
                lo = fmaxf(lo, fminf(t0, t1));
                hi = fminf(hi, fmaxf(t0, t1));
            } else if (b1 < EPSf || b1 > 129.0f - EPSf) {
                empty = true;
            }
            klo = (int)ceilf(lo);
            khi = (int)ceilf(hi);
            if (klo < 0) klo = 0;
            if (khi > N_T) khi = N_T;
            if (empty || khi < klo) { klo = N_T; khi = 0; }
        }

        int wklo = __reduce_min_sync(0xffffffffu, klo);
        int wkhi = __reduce_max_sync(0xffffffffu, khi);

        float accA = 0.0f, accB = 0.0f, accC = 0.0f, accD = 0.0f;

        if (wkhi > wklo) {
            const float bl0 = b0 - 64.0f * (float)h;   // local padded row base
            const float klof = (float)klo;
            const float khif = (float)khi;
            float kf = (float)(wklo + ksub);

            int nit = (wkhi - wklo + 3) >> 2;
            #pragma unroll 2
            for (int it = 0; it < nit; ++it, kf += 4.0f) {
                bool valid = (kf >= klof) && (kf < khif);
                float f0 = fmaf(kf, s0, bl0);
                float f1 = fmaf(kf, s1, b1);
                // safety clamp into tile (invalid lanes read garbage-free, then predicated off)
                f0 = fminf(fmaxf(f0, 0.0f), 64.99f);
                f1 = fminf(fmaxf(f1, 0.0f), 128.99f);
                __half2 rab, rcd;
                SAMPLE(f0, f1, rab, rcd)
                float2 fab = __half22float2(rab);
                float2 fcd = __half22float2(rcd);
                if (valid) {
                    accA += fab.x; accB += fab.y;
                    accC += fcd.x; accD += fcd.y;
                }
            }
        }

        // reduce over the 4 k-lanes of each detector group
        #pragma unroll
        for (int off = 1; off <= 2; off <<= 1) {
            accA += __shfl_xor_sync(0xffffffffu, accA, off);
            accB += __shfl_xor_sync(0xffffffffu, accB, off);
            accC += __shfl_xor_sync(0xffffffffu, accC, off);
            accD += __shfl_xor_sync(0xffffffffu, accD, off);
        }
        if (dok && ksub == 0 && khi > klo) {
            size_t stride = (size_t)N_ANG * N_DET;
            size_t o = ((size_t)(4 * bq) * N_ANG + ang) * N_DET + det;
            atomicAdd(&out[o],              accA * SCALE);
            atomicAdd(&out[o + stride],     accB * SCALE);
            atomicAdd(&out[o + 2 * stride], accC * SCALE);
            atomicAdd(&out[o + 3 * stride], accD * SCALE);
        }
    }
    #undef SAMPLE
}

extern "C" void kernel_launch(void* const* d_in, const int* in_sizes, int n_in,
                              void* d_out, int out_size) {
    const float* x = (const float*)d_in[0];
    float* out = (float*)d_out;
    cudaFuncSetAttribute(radon_fwd_kernel,
                         cudaFuncAttributeMaxDynamicSharedMemorySize, SMEM_BYTES);
    cudaMemsetAsync(d_out, 0, (size_t)out_size * sizeof(float), 0);
    dim3 grid(N_ANG, 2, 2);
    radon_fwd_kernel<<<grid, THREADS, SMEM_BYTES>>>(x, out);
}